// round 12
// baseline (speedup 1.0000x reference)
#include <cuda_runtime.h>

#define NPTS    8192
#define TILE    256
#define NSPLIT  32             // JCHUNK == TILE == 256
#define NIBLK   (NPTS / TILE)  // 32 i-blocks
#define GAMMA_  100.0f         // 1 / sigma^2, sigma = 0.1
#define LOG2E   1.4426950408889634f

// split-K partials: per (split y, point i) two float4 (6 floats used). 8 MB, L2-resident.
__device__ float4 g_part[NSPLIT * NPTS * 2];
__device__ int    g_sem[NIBLK];   // zero-initialized; self-resetting

// smem per j (recentered coords): A = (xt0, xt1, xt2, s2j), s2j = -g*l*|xt_j|^2
//                                  B = (pj0, pj1, pj2, 0)
__global__ __launch_bounds__(TILE)
void lddmm_kernel(const float* __restrict__ mom,
                  const float* __restrict__ x,
                  float* __restrict__ out)
{
    __shared__ float4 sA[TILE];
    __shared__ float4 sB[TILE];
    __shared__ int s_last;

    const int tid   = threadIdx.x;
    const int i     = blockIdx.x * TILE + tid;
    const int jbase = blockIdx.y * TILE;

    // ---- fill tile ----
    {
        const int j = jbase + tid;
        const float a0 = x[3*j] - 0.5f, a1 = x[3*j+1] - 0.5f, a2 = x[3*j+2] - 0.5f;
        const float s2 = -GAMMA_ * LOG2E * (a0*a0 + a1*a1 + a2*a2);
        sA[tid] = make_float4(a0, a1, a2, s2);
        sB[tid] = make_float4(mom[3*j], mom[3*j+1], mom[3*j+2], 0.f);
    }

    // ---- per-i loop invariants (recentered) ----
    const float xt0 = x[3*i] - 0.5f, xt1 = x[3*i+1] - 0.5f, xt2 = x[3*i+2] - 0.5f;
    const float pi0 = mom[3*i], pi1 = mom[3*i+1], pi2 = mom[3*i+2];
    const float g2l = 2.0f * GAMMA_ * LOG2E;
    const float gx0 = g2l * xt0, gx1 = g2l * xt1, gx2 = g2l * xt2;
    const float aiv = -GAMMA_ * LOG2E * (xt0*xt0 + xt1*xt1 + xt2*xt2);

    // accumulate with E = 2^(s2j + gx.xj) = K / Ci,  Ci = 2^aiv  (exact factoring)
    float dx0 = 0.f, dx1 = 0.f, dx2 = 0.f;   // sum E*pj
    float q0  = 0.f, q1  = 0.f, q2  = 0.f;   // sum E*pd*xt_j

    __syncthreads();

    #pragma unroll 8
    for (int k = 0; k < TILE; k++) {
        const float4 XJ = sA[k];             // LDS.128 broadcast
        const float4 PJ = sB[k];

        float arg = fmaf(gx0, XJ.x, XJ.w);   // 3 FFMA, no bias add
        arg = fmaf(gx1, XJ.y, arg);
        arg = fmaf(gx2, XJ.z, arg);

        float Ev;
        asm("ex2.approx.f32 %0, %1;" : "=f"(Ev) : "f"(arg));

        float pd = pi0 * PJ.x;
        pd = fmaf(pi1, PJ.y, pd);
        pd = fmaf(pi2, PJ.z, pd);
        const float w = Ev * pd;

        dx0 = fmaf(Ev, PJ.x, dx0);
        dx1 = fmaf(Ev, PJ.y, dx1);
        dx2 = fmaf(Ev, PJ.z, dx2);
        q0  = fmaf(w, XJ.x, q0);
        q1  = fmaf(w, XJ.y, q1);
        q2  = fmaf(w, XJ.z, q2);
    }

    // ---- finalize this split's partial contribution ----
    const float Ci = exp2f(aiv);
    const float DX0 = Ci * dx0, DX1 = Ci * dx1, DX2 = Ci * dx2;
    const float Q0  = Ci * q0,  Q1  = Ci * q1,  Q2  = Ci * q2;
    const float ws  = pi0 * DX0 + pi1 * DX1 + pi2 * DX2;   // = sum K <pi,pj>
    const float cc  = 2.0f * GAMMA_;

    const int pidx = (blockIdx.y * NPTS + i) * 2;
    g_part[pidx]     = make_float4(cc * fmaf(xt0, ws, -Q0),
                                   cc * fmaf(xt1, ws, -Q1),
                                   cc * fmaf(xt2, ws, -Q2), 0.f);
    g_part[pidx + 1] = make_float4(DX0, DX1, DX2, 0.f);

    // ---- semaphore: last split for this i-block reduces + writes out ----
    __threadfence();
    __syncthreads();
    if (tid == 0)
        s_last = (atomicAdd(&g_sem[blockIdx.x], 1) == NSPLIT - 1) ? 1 : 0;
    __syncthreads();

    if (s_last) {
        float m0 = 0.f, m1 = 0.f, m2 = 0.f, o0 = 0.f, o1 = 0.f, o2 = 0.f;
        #pragma unroll 4
        for (int y = 0; y < NSPLIT; y++) {
            const float4 a = __ldcg(&g_part[(y * NPTS + i) * 2]);
            const float4 b = __ldcg(&g_part[(y * NPTS + i) * 2 + 1]);
            m0 += a.x; m1 += a.y; m2 += a.z;
            o0 += b.x; o1 += b.y; o2 += b.z;
        }
        out[3*i + 0] = m0;                    // dmom
        out[3*i + 1] = m1;
        out[3*i + 2] = m2;
        out[3*NPTS + 3*i + 0] = o0;           // dx
        out[3*NPTS + 3*i + 1] = o1;
        out[3*NPTS + 3*i + 2] = o2;
        if (tid == 0) g_sem[blockIdx.x] = 0;  // reset for next replay
    }
}

extern "C" void kernel_launch(void* const* d_in, const int* in_sizes, int n_in,
                              void* d_out, int out_size)
{
    const float* mom = (const float*)d_in[0];   // [1, 8192, 3]
    const float* x   = (const float*)d_in[1];   // [1, 8192, 3]
    float*       out = (float*)d_out;           // [2, 8192, 3] = dmom | dx

    dim3 grid(NIBLK, NSPLIT);                   // (32, 32) = 1024 CTAs, single launch
    lddmm_kernel<<<grid, TILE>>>(mom, x, out);
}

// round 13
// speedup vs baseline: 1.0375x; 1.0375x over previous
#include <cuda_runtime.h>

#define NPTS    8192
#define TILE    256
#define NSPLIT  32             // JCHUNK == TILE == 256
#define NIBLK   (NPTS / TILE)  // 32 i-blocks
#define GAMMA_  100.0f         // 1 / sigma^2, sigma = 0.1
#define LOG2E   1.4426950408889634f

__device__ int g_flag[NIBLK];  // zero-init; set by y==0 CTA, reset by last arriver
__device__ int g_cnt[NIBLK];   // arrival counter; self-resetting

// smem per j (recentered coords): A = (xt0, xt1, xt2, s2j), s2j = -g*l*|xt_j|^2
//                                  B = (pj0, pj1, pj2, 0)
__global__ __launch_bounds__(TILE)
void lddmm_kernel(const float* __restrict__ mom,
                  const float* __restrict__ x,
                  float* __restrict__ out)
{
    __shared__ float4 sA[TILE];
    __shared__ float4 sB[TILE];

    const int tid   = threadIdx.x;
    const int i     = blockIdx.x * TILE + tid;
    const int jbase = blockIdx.y * TILE;

    // ---- fill tile ----
    {
        const int j = jbase + tid;
        const float a0 = x[3*j] - 0.5f, a1 = x[3*j+1] - 0.5f, a2 = x[3*j+2] - 0.5f;
        const float s2 = -GAMMA_ * LOG2E * (a0*a0 + a1*a1 + a2*a2);
        sA[tid] = make_float4(a0, a1, a2, s2);
        sB[tid] = make_float4(mom[3*j], mom[3*j+1], mom[3*j+2], 0.f);
    }

    // ---- per-i loop invariants (recentered) ----
    const float xt0 = x[3*i] - 0.5f, xt1 = x[3*i+1] - 0.5f, xt2 = x[3*i+2] - 0.5f;
    const float pi0 = mom[3*i], pi1 = mom[3*i+1], pi2 = mom[3*i+2];
    const float g2l = 2.0f * GAMMA_ * LOG2E;
    const float gx0 = g2l * xt0, gx1 = g2l * xt1, gx2 = g2l * xt2;
    const float aiv = -GAMMA_ * LOG2E * (xt0*xt0 + xt1*xt1 + xt2*xt2);

    // accumulate with E = 2^(s2j + gx.xj) = K / Ci,  Ci = 2^aiv  (exact factoring)
    float dx0 = 0.f, dx1 = 0.f, dx2 = 0.f;   // sum E*pj
    float q0  = 0.f, q1  = 0.f, q2  = 0.f;   // sum E*pd*xt_j

    __syncthreads();

    #pragma unroll 8
    for (int k = 0; k < TILE; k++) {
        const float4 XJ = sA[k];             // LDS.128 broadcast
        const float4 PJ = sB[k];

        float arg = fmaf(gx0, XJ.x, XJ.w);   // 3 FFMA, no bias add
        arg = fmaf(gx1, XJ.y, arg);
        arg = fmaf(gx2, XJ.z, arg);

        float Ev;
        asm("ex2.approx.f32 %0, %1;" : "=f"(Ev) : "f"(arg));

        float pd = pi0 * PJ.x;
        pd = fmaf(pi1, PJ.y, pd);
        pd = fmaf(pi2, PJ.z, pd);
        const float w = Ev * pd;

        dx0 = fmaf(Ev, PJ.x, dx0);
        dx1 = fmaf(Ev, PJ.y, dx1);
        dx2 = fmaf(Ev, PJ.z, dx2);
        q0  = fmaf(w, XJ.x, q0);
        q1  = fmaf(w, XJ.y, q1);
        q2  = fmaf(w, XJ.z, q2);
    }

    // ---- epilogue: rescale by Ci, finalize ----
    const float Ci = exp2f(aiv);
    const float DX0 = Ci * dx0, DX1 = Ci * dx1, DX2 = Ci * dx2;
    const float Q0  = Ci * q0,  Q1  = Ci * q1,  Q2  = Ci * q2;
    const float ws  = pi0 * DX0 + pi1 * DX1 + pi2 * DX2;   // = sum K <pi,pj>
    const float cc  = 2.0f * GAMMA_;
    const float M0 = cc * fmaf(xt0, ws, -Q0);
    const float M1 = cc * fmaf(xt1, ws, -Q1);
    const float M2 = cc * fmaf(xt2, ws, -Q2);

    if (blockIdx.y == 0) {
        // owner: overwrite poisoned output with this split's values
        out[3*i + 0] = M0;
        out[3*i + 1] = M1;
        out[3*i + 2] = M2;
        out[3*NPTS + 3*i + 0] = DX0;
        out[3*NPTS + 3*i + 1] = DX1;
        out[3*NPTS + 3*i + 2] = DX2;
        __threadfence();
        __syncthreads();
        if (tid == 0) atomicExch(&g_flag[blockIdx.x], 1);   // release
    } else {
        // wait until owner's stores are visible (loop runs ~0 iters in practice)
        if (tid == 0) while (atomicAdd(&g_flag[blockIdx.x], 0) == 0) {}
        __syncthreads();
        atomicAdd(&out[3*i + 0], M0);
        atomicAdd(&out[3*i + 1], M1);
        atomicAdd(&out[3*i + 2], M2);
        atomicAdd(&out[3*NPTS + 3*i + 0], DX0);
        atomicAdd(&out[3*NPTS + 3*i + 1], DX1);
        atomicAdd(&out[3*NPTS + 3*i + 2], DX2);
    }

    // ---- arrival counter: 32nd CTA resets flag+counter for next replay ----
    __threadfence();
    __syncthreads();
    if (tid == 0) {
        if (atomicAdd(&g_cnt[blockIdx.x], 1) == NSPLIT - 1) {
            g_flag[blockIdx.x] = 0;
            g_cnt[blockIdx.x]  = 0;
            __threadfence();
        }
    }
}

extern "C" void kernel_launch(void* const* d_in, const int* in_sizes, int n_in,
                              void* d_out, int out_size)
{
    const float* mom = (const float*)d_in[0];   // [1, 8192, 3]
    const float* x   = (const float*)d_in[1];   // [1, 8192, 3]
    float*       out = (float*)d_out;           // [2, 8192, 3] = dmom | dx

    dim3 grid(NIBLK, NSPLIT);                   // (32, 32) = 1024 CTAs, single launch
    lddmm_kernel<<<grid, TILE>>>(mom, x, out);
}